// round 7
// baseline (speedup 1.0000x reference)
#include <cuda_runtime.h>
#include <cstddef>

// Problem constants
#define Bb 16
#define Nn 30
#define Tt 50
#define TE 49      // effective timesteps (output drops last)
#define Dd 4
#define Kk 4
#define Hh 128
#define Mm 128
#define Ee 870     // N*(N-1)
#define TCHUNK 7   // 49 = 7 * 7

#define EDGE_SMEM_FLOATS 27080
#define NODE_SMEM_FLOATS 34328

// Scratch: agg[b][t][n][m], t in [0,49)
__device__ float g_agg[(size_t)Bb * TE * Nn * Mm];

// ---------------------------------------------------------------------------
// Edge kernel: block = (t-chunk, receiver n, batch b), 128 threads.
// For 7 timesteps: K=4 edge MLPs over this receiver's 29 edges (padded to
// 32), weighted by rel_type[k], reduced over edges into g_agg.
// Edge e of receiver n has sender j = e + (e >= n); pad edges use rt = 0.
// ---------------------------------------------------------------------------
__global__ __launch_bounds__(128, 2) void edge_kernel(
    const float* __restrict__ inputs,    // (B,N,T,D)
    const float* __restrict__ rel_type,  // (B,E,K)
    const float* __restrict__ W1,        // (K,8,128)
    const float* __restrict__ b1,        // (K,128)
    const float* __restrict__ W2,        // (K,128,128)
    const float* __restrict__ b2)        // (K,128)
{
    extern __shared__ float sm[];
    float* W1s = sm;            // 4096
    float* b1s = sm + 4096;     // 512
    float* b2s = sm + 4608;     // 512
    float* rts = sm + 5120;     // 128   rts[e*4+k], e in [0,32), pad e -> 0
    float* xs  = sm + 5248;     // 840   xs[tt*120 + j*4 + d]
    float* hid = sm + 6088;     // 4608  hid[h*36 + e], e in [0,32), pad 36
    float* W2s = sm + 10696;    // 16384 W2s[h*128 + m]

    const int m  = threadIdx.x;
    const int tc = blockIdx.x;          // 0..6
    const int n  = blockIdx.y;          // 0..29
    const int b  = blockIdx.z;          // 0..15
    const int t0 = tc * TCHUNK;

    // ---- stage invariant data ----
    for (int i = m; i < 4096; i += 128) W1s[i] = W1[i];
    for (int i = m; i < 512;  i += 128) { b1s[i] = b1[i]; b2s[i] = b2[i]; }
    {
        int e = m >> 2, k = m & 3;
        rts[m] = (e < 29) ? rel_type[((size_t)b * Ee + (size_t)n * 29 + e) * Kk + k]
                          : 0.0f;
    }
    for (int i = m; i < TCHUNK * 120; i += 128) {
        int d  = i & 3;
        int j  = (i >> 2) % 30;
        int tt = i / 120;
        xs[i] = inputs[(((size_t)b * Nn + j) * Tt + (t0 + tt)) * Dd + d];
    }

    float acc[TCHUNK];
#pragma unroll
    for (int tt = 0; tt < TCHUNK; ++tt) acc[tt] = 0.0f;

    for (int k = 0; k < Kk; ++k) {
        __syncthreads();   // prior readers of W2s are done
        {
            const float4* src = (const float4*)(W2 + (size_t)k * (Hh * Mm));
            float4* dst = (float4*)W2s;
            for (int i = m; i < 4096; i += 128) dst[i] = src[i];
        }
        __syncthreads();

        float w1r[8];
#pragma unroll
        for (int d = 0; d < 8; ++d) w1r[d] = W1s[(k * 8 + d) * 128 + m];
        const float b1v = b1s[k * 128 + m];
        const float b2v = b2s[k * 128 + m];

        for (int tt = 0; tt < TCHUNK; ++tt) {
            // ---- layer 1: thread m = hidden unit h, loops 32 edges ----
            const float* xrow = xs + tt * 120;
            const float* xr = xrow + n * 4;
            float prer = b1v + xr[0] * w1r[0] + xr[1] * w1r[1]
                             + xr[2] * w1r[2] + xr[3] * w1r[3];
#pragma unroll
            for (int e = 0; e < 32; ++e) {
                int j = (e < n) ? e : ((e < 29) ? e + 1 : 0);  // sender node
                const float* xj = xrow + j * 4;
                float v = prer + xj[0] * w1r[4] + xj[1] * w1r[5]
                               + xj[2] * w1r[6] + xj[3] * w1r[7];
                hid[m * 36 + e] = fmaxf(v, 0.0f);
            }
            __syncthreads();

            // ---- layer 2: thread m = output unit; 32 edges in 4 x 8 ----
            float accl = 0.0f;
#pragma unroll
            for (int eg = 0; eg < 4; ++eg) {
                float a0 = b2v, a1 = b2v, a2 = b2v, a3 = b2v;
                float a4 = b2v, a5 = b2v, a6 = b2v, a7 = b2v;
                const float4* h4 = (const float4*)(hid + eg * 8);
                const float* wc = W2s + m;
#pragma unroll 8
                for (int h = 0; h < 128; ++h) {
                    float  w  = wc[h * 128];
                    float4 u  = h4[h * 9];          // hid[h*36 + eg*8 .. +3]
                    float4 v2 = h4[h * 9 + 1];      // hid[h*36 + eg*8+4 .. +7]
                    a0 += u.x  * w; a1 += u.y  * w; a2 += u.z  * w; a3 += u.w  * w;
                    a4 += v2.x * w; a5 += v2.y * w; a6 += v2.z * w; a7 += v2.w * w;
                }
                const float* r = rts + eg * 32 + k;   // rts[(eg*8+i)*4 + k]
                accl += r[0]  * fmaxf(a0, 0.0f) + r[4]  * fmaxf(a1, 0.0f)
                      + r[8]  * fmaxf(a2, 0.0f) + r[12] * fmaxf(a3, 0.0f)
                      + r[16] * fmaxf(a4, 0.0f) + r[20] * fmaxf(a5, 0.0f)
                      + r[24] * fmaxf(a6, 0.0f) + r[28] * fmaxf(a7, 0.0f);
            }
            acc[tt] += accl;
            __syncthreads();  // before next layer-1 overwrites hid
        }
    }

    for (int tt = 0; tt < TCHUNK; ++tt)
        g_agg[(((size_t)b * TE + (t0 + tt)) * Nn + n) * Mm + m] = acc[tt];
}

// ---------------------------------------------------------------------------
// Node kernel: block = (t, b), 128 threads, loops n = 0..29.
// aug = [x(4), agg(128)] -> relu(oW1) -> relu(oW2) -> oW3 + residual, with
// fused transpose to output layout (B, N, 49, D).
// ---------------------------------------------------------------------------
__global__ __launch_bounds__(128, 1) void node_kernel(
    const float* __restrict__ inputs,
    const float* __restrict__ oW1, const float* __restrict__ ob1,
    const float* __restrict__ oW2, const float* __restrict__ ob2,
    const float* __restrict__ oW3, const float* __restrict__ ob3,
    float* __restrict__ out)
{
    extern __shared__ float sm[];
    float* oW1s = sm;             // 16896  (132 x 128)
    float* oW2s = sm + 16896;     // 16384
    float* oW3s = sm + 33280;     // 512    (128 x 4)
    float* ob1s = sm + 33792;     // 128
    float* ob2s = sm + 33920;     // 128
    float* ob3s = sm + 34048;     // 4
    float* augs = sm + 34052;     // 132
    float* h1s  = sm + 34184;     // 128
    float* red  = sm + 34312;     // 16

    const int m = threadIdx.x;
    const int t = blockIdx.x;   // 0..48
    const int b = blockIdx.y;   // 0..15
    const int lane = m & 31, wid = m >> 5;

    for (int i = m; i < 16896; i += 128) oW1s[i] = oW1[i];
    for (int i = m; i < 16384; i += 128) oW2s[i] = oW2[i];
    for (int i = m; i < 512;   i += 128) oW3s[i] = oW3[i];
    ob1s[m] = ob1[m];
    ob2s[m] = ob2[m];
    if (m < 4) ob3s[m] = ob3[m];
    __syncthreads();

    for (int n = 0; n < Nn; ++n) {
        const float* xptr = inputs + (((size_t)b * Nn + n) * Tt + t) * Dd;
        augs[4 + m] = g_agg[(((size_t)b * TE + t) * Nn + n) * Mm + m];
        if (m < 4) augs[m] = xptr[m];
        __syncthreads();

        float h1 = ob1s[m];
#pragma unroll 4
        for (int i = 0; i < 132; ++i) h1 += augs[i] * oW1s[i * 128 + m];
        h1s[m] = fmaxf(h1, 0.0f);
        __syncthreads();

        float h2 = ob2s[m];
#pragma unroll 4
        for (int i = 0; i < 128; ++i) h2 += h1s[i] * oW2s[i * 128 + m];
        h2 = fmaxf(h2, 0.0f);

        float p0 = h2 * oW3s[m * 4 + 0];
        float p1 = h2 * oW3s[m * 4 + 1];
        float p2 = h2 * oW3s[m * 4 + 2];
        float p3 = h2 * oW3s[m * 4 + 3];
#pragma unroll
        for (int off = 16; off > 0; off >>= 1) {
            p0 += __shfl_down_sync(0xffffffffu, p0, off);
            p1 += __shfl_down_sync(0xffffffffu, p1, off);
            p2 += __shfl_down_sync(0xffffffffu, p2, off);
            p3 += __shfl_down_sync(0xffffffffu, p3, off);
        }
        if (lane == 0) {
            red[wid * 4 + 0] = p0; red[wid * 4 + 1] = p1;
            red[wid * 4 + 2] = p2; red[wid * 4 + 3] = p3;
        }
        __syncthreads();
        if (m < 4) {
            float v = red[m] + red[4 + m] + red[8 + m] + red[12 + m] + ob3s[m];
            out[(((size_t)b * Nn + n) * TE + t) * Dd + m] = augs[m] + v;
        }
        __syncthreads();   // before next n overwrites augs/h1s/red
    }
}

extern "C" void kernel_launch(void* const* d_in, const int* in_sizes, int n_in,
                              void* d_out, int out_size)
{
    (void)in_sizes; (void)n_in; (void)out_size;
    const float* inputs   = (const float*)d_in[0];
    const float* rel_type = (const float*)d_in[1];
    // d_in[2] = rel_rec, d_in[3] = rel_send: structure known analytically, unused.
    const float* W1  = (const float*)d_in[4];
    const float* b1  = (const float*)d_in[5];
    const float* W2  = (const float*)d_in[6];
    const float* b2  = (const float*)d_in[7];
    const float* oW1 = (const float*)d_in[8];
    const float* ob1 = (const float*)d_in[9];
    const float* oW2 = (const float*)d_in[10];
    const float* ob2 = (const float*)d_in[11];
    const float* oW3 = (const float*)d_in[12];
    const float* ob3 = (const float*)d_in[13];
    float* out = (float*)d_out;

    cudaFuncSetAttribute(edge_kernel, cudaFuncAttributeMaxDynamicSharedMemorySize,
                         EDGE_SMEM_FLOATS * 4);
    cudaFuncSetAttribute(node_kernel, cudaFuncAttributeMaxDynamicSharedMemorySize,
                         NODE_SMEM_FLOATS * 4);

    dim3 egrid(TE / TCHUNK, Nn, Bb);   // (7, 30, 16)
    edge_kernel<<<egrid, 128, EDGE_SMEM_FLOATS * 4>>>(inputs, rel_type,
                                                      W1, b1, W2, b2);
    dim3 ngrid(TE, Bb);                // (49, 16)
    node_kernel<<<ngrid, 128, NODE_SMEM_FLOATS * 4>>>(inputs, oW1, ob1, oW2, ob2,
                                                      oW3, ob3, out);
}

// round 9
// speedup vs baseline: 1.2891x; 1.2891x over previous
#include <cuda_runtime.h>
#include <cstdint>
#include <cstddef>

// Problem constants
#define Bb 16
#define Nn 30
#define Tt 50
#define TE 49      // effective timesteps (output drops last)
#define Dd 4
#define Kk 4
#define Hh 128
#define Mm 128
#define Ee 870     // N*(N-1)
#define TCHUNK 7   // 49 = 7 * 7

#define EDGE_SMEM_FLOATS 27080
#define NODE_SMEM_FLOATS 35156

#define FMA2(d, a, b) \
    asm("fma.rn.f32x2 %0, %1, %2, %0;" : "+l"(d) : "l"(a), "l"(b))

// Scratch: agg[b][t][n][m], t in [0,49)
__device__ float g_agg[(size_t)Bb * TE * Nn * Mm];

// ---------------------------------------------------------------------------
// Edge kernel: block = (t-chunk, receiver n, batch b), 128 threads.
// For 7 timesteps: K=4 edge MLPs over this receiver's 29 edges (padded to
// 32), weighted by rel_type[k], reduced over edges into g_agg.
// Edge e of receiver n has sender j = e + (e >= n); pad edges use rt = 0.
// Layer 2 uses packed f32x2 FMA: 32 edges = 16 two-wide accumulators.
// ---------------------------------------------------------------------------
__global__ __launch_bounds__(128, 2) void edge_kernel(
    const float* __restrict__ inputs,    // (B,N,T,D)
    const float* __restrict__ rel_type,  // (B,E,K)
    const float* __restrict__ W1,        // (K,8,128)
    const float* __restrict__ b1,        // (K,128)
    const float* __restrict__ W2,        // (K,128,128)
    const float* __restrict__ b2)        // (K,128)
{
    extern __shared__ float sm[];
    float* W1s = sm;            // 4096
    float* b1s = sm + 4096;     // 512
    float* b2s = sm + 4608;     // 512
    float* rts = sm + 5120;     // 128   rts[e*4+k], e in [0,32), pad e -> 0
    float* xs  = sm + 5248;     // 840   xs[tt*120 + j*4 + d]
    float* hid = sm + 6088;     // 4608  hid[h*36 + e], e in [0,32), pad to 36
    float* W2s = sm + 10696;    // 16384 W2s[h*128 + m]

    const int m  = threadIdx.x;
    const int tc = blockIdx.x;          // 0..6
    const int n  = blockIdx.y;          // 0..29
    const int b  = blockIdx.z;          // 0..15
    const int t0 = tc * TCHUNK;

    // ---- stage invariant data ----
    for (int i = m; i < 4096; i += 128) W1s[i] = W1[i];
    for (int i = m; i < 512;  i += 128) { b1s[i] = b1[i]; b2s[i] = b2[i]; }
    {
        int e = m >> 2, k = m & 3;
        rts[m] = (e < 29) ? rel_type[((size_t)b * Ee + (size_t)n * 29 + e) * Kk + k]
                          : 0.0f;
    }
    for (int i = m; i < TCHUNK * 120; i += 128) {
        int d  = i & 3;
        int j  = (i >> 2) % 30;
        int tt = i / 120;
        xs[i] = inputs[(((size_t)b * Nn + j) * Tt + (t0 + tt)) * Dd + d];
    }

    float acc[TCHUNK];
#pragma unroll
    for (int tt = 0; tt < TCHUNK; ++tt) acc[tt] = 0.0f;

    for (int k = 0; k < Kk; ++k) {
        __syncthreads();   // prior readers of W2s are done
        {
            const float4* src = (const float4*)(W2 + (size_t)k * (Hh * Mm));
            float4* dst = (float4*)W2s;
            for (int i = m; i < 4096; i += 128) dst[i] = src[i];
        }
        __syncthreads();

        float w1r[8];
#pragma unroll
        for (int d = 0; d < 8; ++d) w1r[d] = W1s[(k * 8 + d) * 128 + m];
        const float b1v = b1s[k * 128 + m];
        const float b2v = b2s[k * 128 + m];

        unsigned long long b2pack;
        {
            uint32_t b2bits = __float_as_uint(b2v);
            asm("mov.b64 %0, {%1, %1};" : "=l"(b2pack) : "r"(b2bits));
        }

        for (int tt = 0; tt < TCHUNK; ++tt) {
            // ---- layer 1: thread m = hidden unit h, loops 32 edges ----
            const float* xrow = xs + tt * 120;
            const float* xr = xrow + n * 4;
            float prer = b1v + xr[0] * w1r[0] + xr[1] * w1r[1]
                             + xr[2] * w1r[2] + xr[3] * w1r[3];
#pragma unroll
            for (int e = 0; e < 32; ++e) {
                int j = (e < n) ? e : ((e < 29) ? e + 1 : 0);  // sender node
                const float* xj = xrow + j * 4;
                float v = prer + xj[0] * w1r[4] + xj[1] * w1r[5]
                               + xj[2] * w1r[6] + xj[3] * w1r[7];
                hid[m * 36 + e] = fmaxf(v, 0.0f);
            }
            __syncthreads();

            // ---- layer 2: thread m = output unit; 16 f32x2 accumulators ----
            unsigned long long acc2[16];
#pragma unroll
            for (int i = 0; i < 16; ++i) acc2[i] = b2pack;

            const ulonglong2* h4 = (const ulonglong2*)hid;  // row = 9 u64x2
            const float* wc = W2s + m;
#pragma unroll 8
            for (int h = 0; h < 128; ++h) {
                uint32_t wb = __float_as_uint(wc[h * 128]);
                unsigned long long w2p;
                asm("mov.b64 %0, {%1, %1};" : "=l"(w2p) : "r"(wb));
                ulonglong2 u0 = h4[h * 9 + 0];   // edges 0..3
                ulonglong2 u1 = h4[h * 9 + 1];   // edges 4..7
                ulonglong2 u2 = h4[h * 9 + 2];   // edges 8..11
                ulonglong2 u3 = h4[h * 9 + 3];   // edges 12..15
                FMA2(acc2[0], u0.x, w2p); FMA2(acc2[1], u0.y, w2p);
                FMA2(acc2[2], u1.x, w2p); FMA2(acc2[3], u1.y, w2p);
                FMA2(acc2[4], u2.x, w2p); FMA2(acc2[5], u2.y, w2p);
                FMA2(acc2[6], u3.x, w2p); FMA2(acc2[7], u3.y, w2p);
                ulonglong2 u4 = h4[h * 9 + 4];   // edges 16..19
                ulonglong2 u5 = h4[h * 9 + 5];   // edges 20..23
                ulonglong2 u6 = h4[h * 9 + 6];   // edges 24..27
                ulonglong2 u7 = h4[h * 9 + 7];   // edges 28..31
                FMA2(acc2[8],  u4.x, w2p); FMA2(acc2[9],  u4.y, w2p);
                FMA2(acc2[10], u5.x, w2p); FMA2(acc2[11], u5.y, w2p);
                FMA2(acc2[12], u6.x, w2p); FMA2(acc2[13], u6.y, w2p);
                FMA2(acc2[14], u7.x, w2p); FMA2(acc2[15], u7.y, w2p);
            }

            float accl = 0.0f;
#pragma unroll
            for (int i = 0; i < 16; ++i) {
                uint32_t lo, hi;
                asm("mov.b64 {%0, %1}, %2;" : "=r"(lo), "=r"(hi) : "l"(acc2[i]));
                accl += rts[(2 * i) * 4 + k]     * fmaxf(__uint_as_float(lo), 0.0f);
                accl += rts[(2 * i + 1) * 4 + k] * fmaxf(__uint_as_float(hi), 0.0f);
            }
            acc[tt] += accl;
            __syncthreads();  // before next layer-1 overwrites hid
        }
    }

    for (int tt = 0; tt < TCHUNK; ++tt)
        g_agg[(((size_t)b * TE + (t0 + tt)) * Nn + n) * Mm + m] = acc[tt];
}

// ---------------------------------------------------------------------------
// Node kernel: block = (t, b), 512 threads = 4 node-groups of 128.
// Each group g handles node n = it*4 + g over 8 iterations (n < 30 guard).
// aug = [x(4), agg(128)] -> relu(oW1) -> relu(oW2) -> oW3 + residual, fused
// transpose to output layout (B, N, 49, D). 4-way split accumulators.
// ---------------------------------------------------------------------------
__global__ __launch_bounds__(512, 1) void node_kernel(
    const float* __restrict__ inputs,
    const float* __restrict__ oW1, const float* __restrict__ ob1,
    const float* __restrict__ oW2, const float* __restrict__ ob2,
    const float* __restrict__ oW3, const float* __restrict__ ob3,
    float* __restrict__ out)
{
    extern __shared__ float sm[];
    float* oW1s = sm;             // 16896  (132 x 128)
    float* oW2s = sm + 16896;     // 16384
    float* oW3s = sm + 33280;     // 512    (128 x 4)
    float* ob1s = sm + 33792;     // 128
    float* ob2s = sm + 33920;     // 128
    float* ob3s = sm + 34048;     // 4
    float* augs = sm + 34052;     // 528 = 4 x 132
    float* h1s  = sm + 34580;     // 512 = 4 x 128
    float* red  = sm + 35092;     // 64  = 4 x 16

    const int tid = threadIdx.x;
    const int g   = tid >> 7;      // node group 0..3
    const int m   = tid & 127;
    const int t   = blockIdx.x;    // 0..48
    const int b   = blockIdx.y;    // 0..15
    const int lane = m & 31, wgrp = (m >> 5);

    for (int i = tid; i < 16896; i += 512) oW1s[i] = oW1[i];
    for (int i = tid; i < 16384; i += 512) oW2s[i] = oW2[i];
    for (int i = tid; i < 512;   i += 512) oW3s[i] = oW3[i];
    if (tid < 128) ob1s[tid] = ob1[tid];
    else if (tid < 256) ob2s[tid - 128] = ob2[tid - 128];
    else if (tid < 260) ob3s[tid - 256] = ob3[tid - 256];
    __syncthreads();

    float* aug = augs + g * 132;
    float* h1v = h1s  + g * 128;
    float* rd  = red  + g * 16;

    for (int it = 0; it < 8; ++it) {
        const int n = it * 4 + g;           // 0..31
        const bool act = (n < Nn);

        if (act) {
            aug[4 + m] = g_agg[(((size_t)b * TE + t) * Nn + n) * Mm + m];
            if (m < 4)
                aug[m] = inputs[(((size_t)b * Nn + n) * Tt + t) * Dd + m];
        }
        __syncthreads();

        if (act) {
            float s0 = 0.f, s1 = 0.f, s2 = 0.f, s3 = 0.f;
#pragma unroll 8
            for (int i = 0; i < 132; i += 4) {
                s0 += aug[i + 0] * oW1s[(i + 0) * 128 + m];
                s1 += aug[i + 1] * oW1s[(i + 1) * 128 + m];
                s2 += aug[i + 2] * oW1s[(i + 2) * 128 + m];
                s3 += aug[i + 3] * oW1s[(i + 3) * 128 + m];
            }
            h1v[m] = fmaxf(ob1s[m] + ((s0 + s1) + (s2 + s3)), 0.0f);
        }
        __syncthreads();

        float h2 = 0.0f;
        if (act) {
            float s0 = 0.f, s1 = 0.f, s2 = 0.f, s3 = 0.f;
#pragma unroll 8
            for (int i = 0; i < 128; i += 4) {
                s0 += h1v[i + 0] * oW2s[(i + 0) * 128 + m];
                s1 += h1v[i + 1] * oW2s[(i + 1) * 128 + m];
                s2 += h1v[i + 2] * oW2s[(i + 2) * 128 + m];
                s3 += h1v[i + 3] * oW2s[(i + 3) * 128 + m];
            }
            h2 = fmaxf(ob2s[m] + ((s0 + s1) + (s2 + s3)), 0.0f);
        }

        float p0 = h2 * oW3s[m * 4 + 0];
        float p1 = h2 * oW3s[m * 4 + 1];
        float p2 = h2 * oW3s[m * 4 + 2];
        float p3 = h2 * oW3s[m * 4 + 3];
#pragma unroll
        for (int off = 16; off > 0; off >>= 1) {
            p0 += __shfl_down_sync(0xffffffffu, p0, off);
            p1 += __shfl_down_sync(0xffffffffu, p1, off);
            p2 += __shfl_down_sync(0xffffffffu, p2, off);
            p3 += __shfl_down_sync(0xffffffffu, p3, off);
        }
        if (lane == 0) {
            rd[wgrp * 4 + 0] = p0; rd[wgrp * 4 + 1] = p1;
            rd[wgrp * 4 + 2] = p2; rd[wgrp * 4 + 3] = p3;
        }
        __syncthreads();
        if (act && m < 4) {
            float v = rd[m] + rd[4 + m] + rd[8 + m] + rd[12 + m] + ob3s[m];
            out[(((size_t)b * Nn + n) * TE + t) * Dd + m] = aug[m] + v;
        }
        __syncthreads();   // before next it overwrites aug/h1v/rd
    }
}

extern "C" void kernel_launch(void* const* d_in, const int* in_sizes, int n_in,
                              void* d_out, int out_size)
{
    (void)in_sizes; (void)n_in; (void)out_size;
    const float* inputs   = (const float*)d_in[0];
    const float* rel_type = (const float*)d_in[1];
    // d_in[2] = rel_rec, d_in[3] = rel_send: structure known analytically, unused.
    const float* W1  = (const float*)d_in[4];
    const float* b1  = (const float*)d_in[5];
    const float* W2  = (const float*)d_in[6];
    const float* b2  = (const float*)d_in[7];
    const float* oW1 = (const float*)d_in[8];
    const float* ob1 = (const float*)d_in[9];
    const float* oW2 = (const float*)d_in[10];
    const float* ob2 = (const float*)d_in[11];
    const float* oW3 = (const float*)d_in[12];
    const float* ob3 = (const float*)d_in[13];
    float* out = (float*)d_out;

    cudaFuncSetAttribute(edge_kernel, cudaFuncAttributeMaxDynamicSharedMemorySize,
                         EDGE_SMEM_FLOATS * 4);
    cudaFuncSetAttribute(node_kernel, cudaFuncAttributeMaxDynamicSharedMemorySize,
                         NODE_SMEM_FLOATS * 4);

    dim3 egrid(TE / TCHUNK, Nn, Bb);   // (7, 30, 16)
    edge_kernel<<<egrid, 128, EDGE_SMEM_FLOATS * 4>>>(inputs, rel_type,
                                                      W1, b1, W2, b2);
    dim3 ngrid(TE, Bb);                // (49, 16)
    node_kernel<<<ngrid, 512, NODE_SMEM_FLOATS * 4>>>(inputs, oW1, ob1, oW2, ob2,
                                                      oW3, ob3, out);
}

// round 10
// speedup vs baseline: 1.9926x; 1.5458x over previous
#include <cuda_runtime.h>
#include <cstdint>
#include <cstddef>

// Problem constants
#define Bb 16
#define Nn 30
#define Tt 50
#define TE 49      // effective timesteps (output drops last)
#define Dd 4
#define Kk 4
#define Hh 128
#define Mm 128
#define Ee 870     // N*(N-1)
#define TCHUNK 7   // 49 = 7 * 7

#define EDGE_SMEM_FLOATS 27080
#define NODE_SMEM_FLOATS 35156

#define FMA2(d, a, b) \
    asm("fma.rn.f32x2 %0, %1, %2, %0;" : "+l"(d) : "l"(a), "l"(b))
#define PACK2(d, s) \
    asm("mov.b64 %0, {%1, %1};" : "=l"(d) : "r"(s))
#define UNPACK2(lo, hi, s) \
    asm("mov.b64 {%0, %1}, %2;" : "=r"(lo), "=r"(hi) : "l"(s))

// Scratch: agg[b][t][n][m], t in [0,49)
__device__ float g_agg[(size_t)Bb * TE * Nn * Mm];

// ---------------------------------------------------------------------------
// Edge kernel: block = (t-chunk, receiver n, batch b), 128 threads.
// Layer 1: thread m computes hid[m][e] for 32 edges (29 real + 3 pad).
// Layer 2 mapping: warp w owns edges 8w..8w+7; lane l owns outputs
// m = 4l..4l+3. Per h: 2 broadcast LDS128 (hid pairs) + 1 float4 LDS (W2
// row) + 16 f32x2 FMA. Each (m, edge) lives in one thread; bias+relu+rt
// weighting per thread; partials reduced across warps once per tt at end.
// ---------------------------------------------------------------------------
__global__ __launch_bounds__(128, 2) void edge_kernel(
    const float* __restrict__ inputs,    // (B,N,T,D)
    const float* __restrict__ rel_type,  // (B,E,K)
    const float* __restrict__ W1,        // (K,8,128)
    const float* __restrict__ b1,        // (K,128)
    const float* __restrict__ W2,        // (K,128,128)
    const float* __restrict__ b2)        // (K,128)
{
    extern __shared__ float sm[];
    float* W1s = sm;            // 4096
    float* b1s = sm + 4096;     // 512
    float* b2s = sm + 4608;     // 512
    float* rts = sm + 5120;     // 128   rts[e*4+k], e in [0,32), pad e -> 0
    float* xs  = sm + 5248;     // 840   xs[tt*120 + j*4 + d]
    float* hid = sm + 6088;     // 4608  hid[h*36 + e]; reused as red[4][128]
    float* W2s = sm + 10696;    // 16384 W2s[h*128 + m]

    const int m    = threadIdx.x;
    const int lane = m & 31;
    const int wrp  = m >> 5;            // 0..3, owns edges 8w..8w+7
    const int tc = blockIdx.x;          // 0..6
    const int n  = blockIdx.y;          // 0..29
    const int b  = blockIdx.z;          // 0..15
    const int t0 = tc * TCHUNK;

    // ---- stage invariant data ----
    for (int i = m; i < 4096; i += 128) W1s[i] = W1[i];
    for (int i = m; i < 512;  i += 128) { b1s[i] = b1[i]; b2s[i] = b2[i]; }
    {
        int e = m >> 2, k = m & 3;
        rts[m] = (e < 29) ? rel_type[((size_t)b * Ee + (size_t)n * 29 + e) * Kk + k]
                          : 0.0f;
    }
    for (int i = m; i < TCHUNK * 120; i += 128) {
        int d  = i & 3;
        int j  = (i >> 2) % 30;
        int tt = i / 120;
        xs[i] = inputs[(((size_t)b * Nn + j) * Tt + (t0 + tt)) * Dd + d];
    }

    // Per-thread partial sums: acc[tt*4+j] for m_out = 4*lane + j,
    // summed over this warp's 8 edges and all k.
    float acc[TCHUNK * 4];
#pragma unroll
    for (int i = 0; i < TCHUNK * 4; ++i) acc[i] = 0.0f;

    for (int k = 0; k < Kk; ++k) {
        __syncthreads();   // prior readers of W2s / hid are done
        {
            const float4* src = (const float4*)(W2 + (size_t)k * (Hh * Mm));
            float4* dst = (float4*)W2s;
            for (int i = m; i < 4096; i += 128) dst[i] = src[i];
        }
        __syncthreads();

        float w1r[8];
#pragma unroll
        for (int d = 0; d < 8; ++d) w1r[d] = W1s[(k * 8 + d) * 128 + m];
        const float b1v = b1s[k * 128 + m];

        // Layer-2 per-thread constants for this k
        float4 b2v4 = *(const float4*)(b2s + k * 128 + (lane << 2));
        unsigned long long b2p[4];
        PACK2(b2p[0], __float_as_uint(b2v4.x));
        PACK2(b2p[1], __float_as_uint(b2v4.y));
        PACK2(b2p[2], __float_as_uint(b2v4.z));
        PACK2(b2p[3], __float_as_uint(b2v4.w));
        float rtreg[8];
#pragma unroll
        for (int i = 0; i < 8; ++i) rtreg[i] = rts[(8 * wrp + i) * 4 + k];

        for (int tt = 0; tt < TCHUNK; ++tt) {
            // ---- layer 1: thread m = hidden unit, loops 32 edges ----
            const float* xrow = xs + tt * 120;
            const float* xr = xrow + n * 4;
            float prer = b1v + xr[0] * w1r[0] + xr[1] * w1r[1]
                             + xr[2] * w1r[2] + xr[3] * w1r[3];
#pragma unroll
            for (int e = 0; e < 32; ++e) {
                int j = (e < n) ? e : ((e < 29) ? e + 1 : 0);  // sender node
                const float* xj = xrow + j * 4;
                float v = prer + xj[0] * w1r[4] + xj[1] * w1r[5]
                               + xj[2] * w1r[6] + xj[3] * w1r[7];
                hid[m * 36 + e] = fmaxf(v, 0.0f);
            }
            __syncthreads();

            // ---- layer 2 ----
            // acc2[j*4+p]: output m=4*lane+j, edge pair p (edges 8w+2p, +1)
            unsigned long long acc2[16];
#pragma unroll
            for (int j = 0; j < 4; ++j) {
                acc2[j * 4 + 0] = b2p[j]; acc2[j * 4 + 1] = b2p[j];
                acc2[j * 4 + 2] = b2p[j]; acc2[j * 4 + 3] = b2p[j];
            }
            const float* hbase = hid + 8 * wrp;
            const float* wbase = W2s + (lane << 2);
#pragma unroll 16
            for (int h = 0; h < 128; ++h) {
                ulonglong2 u0 = *(const ulonglong2*)(hbase + h * 36);
                ulonglong2 u1 = *(const ulonglong2*)(hbase + h * 36 + 4);
                float4 wv = *(const float4*)(wbase + h * 128);
                unsigned long long w0, w1, w2, w3;
                PACK2(w0, __float_as_uint(wv.x));
                PACK2(w1, __float_as_uint(wv.y));
                PACK2(w2, __float_as_uint(wv.z));
                PACK2(w3, __float_as_uint(wv.w));
                FMA2(acc2[0],  u0.x, w0); FMA2(acc2[1],  u0.y, w0);
                FMA2(acc2[2],  u1.x, w0); FMA2(acc2[3],  u1.y, w0);
                FMA2(acc2[4],  u0.x, w1); FMA2(acc2[5],  u0.y, w1);
                FMA2(acc2[6],  u1.x, w1); FMA2(acc2[7],  u1.y, w1);
                FMA2(acc2[8],  u0.x, w2); FMA2(acc2[9],  u0.y, w2);
                FMA2(acc2[10], u1.x, w2); FMA2(acc2[11], u1.y, w2);
                FMA2(acc2[12], u0.x, w3); FMA2(acc2[13], u0.y, w3);
                FMA2(acc2[14], u1.x, w3); FMA2(acc2[15], u1.y, w3);
            }

            // epilogue: relu + rt weight, accumulate 8-edge partial per m
#pragma unroll
            for (int j = 0; j < 4; ++j) {
                float a = 0.0f;
#pragma unroll
                for (int p = 0; p < 4; ++p) {
                    uint32_t lo, hi;
                    UNPACK2(lo, hi, acc2[j * 4 + p]);
                    a += rtreg[2 * p]     * fmaxf(__uint_as_float(lo), 0.0f);
                    a += rtreg[2 * p + 1] * fmaxf(__uint_as_float(hi), 0.0f);
                }
                acc[tt * 4 + j] += a;
            }
            __syncthreads();  // before next layer-1 overwrites hid
        }
    }

    // ---- cross-warp reduction: g_agg[m] = sum over 4 warps' partials ----
    float* red = hid;   // reuse, 4*128 floats
    for (int tt = 0; tt < TCHUNK; ++tt) {
        __syncthreads();
        *(float4*)(red + wrp * 128 + (lane << 2)) =
            make_float4(acc[tt * 4 + 0], acc[tt * 4 + 1],
                        acc[tt * 4 + 2], acc[tt * 4 + 3]);
        __syncthreads();
        float v = red[m] + red[128 + m] + red[256 + m] + red[384 + m];
        g_agg[(((size_t)b * TE + (t0 + tt)) * Nn + n) * Mm + m] = v;
    }
}

// ---------------------------------------------------------------------------
// Node kernel: block = (t, b), 512 threads = 4 node-groups of 128.
// ---------------------------------------------------------------------------
__global__ __launch_bounds__(512, 1) void node_kernel(
    const float* __restrict__ inputs,
    const float* __restrict__ oW1, const float* __restrict__ ob1,
    const float* __restrict__ oW2, const float* __restrict__ ob2,
    const float* __restrict__ oW3, const float* __restrict__ ob3,
    float* __restrict__ out)
{
    extern __shared__ float sm[];
    float* oW1s = sm;             // 16896  (132 x 128)
    float* oW2s = sm + 16896;     // 16384
    float* oW3s = sm + 33280;     // 512    (128 x 4)
    float* ob1s = sm + 33792;     // 128
    float* ob2s = sm + 33920;     // 128
    float* ob3s = sm + 34048;     // 4
    float* augs = sm + 34052;     // 528 = 4 x 132
    float* h1s  = sm + 34580;     // 512 = 4 x 128
    float* red  = sm + 35092;     // 64  = 4 x 16

    const int tid = threadIdx.x;
    const int g   = tid >> 7;      // node group 0..3
    const int m   = tid & 127;
    const int t   = blockIdx.x;    // 0..48
    const int b   = blockIdx.y;    // 0..15
    const int lane = m & 31, wgrp = (m >> 5);

    for (int i = tid; i < 16896; i += 512) oW1s[i] = oW1[i];
    for (int i = tid; i < 16384; i += 512) oW2s[i] = oW2[i];
    for (int i = tid; i < 512;   i += 512) oW3s[i] = oW3[i];
    if (tid < 128) ob1s[tid] = ob1[tid];
    else if (tid < 256) ob2s[tid - 128] = ob2[tid - 128];
    else if (tid < 260) ob3s[tid - 256] = ob3[tid - 256];
    __syncthreads();

    float* aug = augs + g * 132;
    float* h1v = h1s  + g * 128;
    float* rd  = red  + g * 16;

    for (int it = 0; it < 8; ++it) {
        const int n = it * 4 + g;           // 0..31
        const bool act = (n < Nn);

        if (act) {
            aug[4 + m] = g_agg[(((size_t)b * TE + t) * Nn + n) * Mm + m];
            if (m < 4)
                aug[m] = inputs[(((size_t)b * Nn + n) * Tt + t) * Dd + m];
        }
        __syncthreads();

        if (act) {
            float s0 = 0.f, s1 = 0.f, s2 = 0.f, s3 = 0.f;
#pragma unroll 8
            for (int i = 0; i < 132; i += 4) {
                s0 += aug[i + 0] * oW1s[(i + 0) * 128 + m];
                s1 += aug[i + 1] * oW1s[(i + 1) * 128 + m];
                s2 += aug[i + 2] * oW1s[(i + 2) * 128 + m];
                s3 += aug[i + 3] * oW1s[(i + 3) * 128 + m];
            }
            h1v[m] = fmaxf(ob1s[m] + ((s0 + s1) + (s2 + s3)), 0.0f);
        }
        __syncthreads();

        float h2 = 0.0f;
        if (act) {
            float s0 = 0.f, s1 = 0.f, s2 = 0.f, s3 = 0.f;
#pragma unroll 8
            for (int i = 0; i < 128; i += 4) {
                s0 += h1v[i + 0] * oW2s[(i + 0) * 128 + m];
                s1 += h1v[i + 1] * oW2s[(i + 1) * 128 + m];
                s2 += h1v[i + 2] * oW2s[(i + 2) * 128 + m];
                s3 += h1v[i + 3] * oW2s[(i + 3) * 128 + m];
            }
            h2 = fmaxf(ob2s[m] + ((s0 + s1) + (s2 + s3)), 0.0f);
        }

        float p0 = h2 * oW3s[m * 4 + 0];
        float p1 = h2 * oW3s[m * 4 + 1];
        float p2 = h2 * oW3s[m * 4 + 2];
        float p3 = h2 * oW3s[m * 4 + 3];
#pragma unroll
        for (int off = 16; off > 0; off >>= 1) {
            p0 += __shfl_down_sync(0xffffffffu, p0, off);
            p1 += __shfl_down_sync(0xffffffffu, p1, off);
            p2 += __shfl_down_sync(0xffffffffu, p2, off);
            p3 += __shfl_down_sync(0xffffffffu, p3, off);
        }
        if (lane == 0) {
            rd[wgrp * 4 + 0] = p0; rd[wgrp * 4 + 1] = p1;
            rd[wgrp * 4 + 2] = p2; rd[wgrp * 4 + 3] = p3;
        }
        __syncthreads();
        if (act && m < 4) {
            float v = rd[m] + rd[4 + m] + rd[8 + m] + rd[12 + m] + ob3s[m];
            out[(((size_t)b * Nn + n) * TE + t) * Dd + m] = aug[m] + v;
        }
        __syncthreads();   // before next it overwrites aug/h1v/rd
    }
}

extern "C" void kernel_launch(void* const* d_in, const int* in_sizes, int n_in,
                              void* d_out, int out_size)
{
    (void)in_sizes; (void)n_in; (void)out_size;
    const float* inputs   = (const float*)d_in[0];
    const float* rel_type = (const float*)d_in[1];
    // d_in[2] = rel_rec, d_in[3] = rel_send: structure known analytically, unused.
    const float* W1  = (const float*)d_in[4];
    const float* b1  = (const float*)d_in[5];
    const float* W2  = (const float*)d_in[6];
    const float* b2  = (const float*)d_in[7];
    const float* oW1 = (const float*)d_in[8];
    const float* ob1 = (const float*)d_in[9];
    const float* oW2 = (const float*)d_in[10];
    const float* ob2 = (const float*)d_in[11];
    const float* oW3 = (const float*)d_in[12];
    const float* ob3 = (const float*)d_in[13];
    float* out = (float*)d_out;

    cudaFuncSetAttribute(edge_kernel, cudaFuncAttributeMaxDynamicSharedMemorySize,
                         EDGE_SMEM_FLOATS * 4);
    cudaFuncSetAttribute(node_kernel, cudaFuncAttributeMaxDynamicSharedMemorySize,
                         NODE_SMEM_FLOATS * 4);

    dim3 egrid(TE / TCHUNK, Nn, Bb);   // (7, 30, 16)
    edge_kernel<<<egrid, 128, EDGE_SMEM_FLOATS * 4>>>(inputs, rel_type,
                                                      W1, b1, W2, b2);
    dim3 ngrid(TE, Bb);                // (49, 16)
    node_kernel<<<ngrid, 512, NODE_SMEM_FLOATS * 4>>>(inputs, oW1, ob1, oW2, ob2,
                                                      oW3, ob3, out);
}